// round 2
// baseline (speedup 1.0000x reference)
#include <cuda_runtime.h>
#include <cuda_bf16.h>
#include <math.h>

// Problem constants
#define B_    4
#define SQ_   1024
#define SKV_  4096
#define DQ_   1024
#define DKV_  768
#define H_    16
#define DH_   64
#define DOUT_ 256

// ---------------------------------------------------------------------------
// Scratch (static device globals — no runtime allocation allowed)
// ---------------------------------------------------------------------------
__device__ float g_q  [(size_t)B_ * SQ_  * DQ_];   // projected q  [B,SQ,H*DH]
__device__ float g_k  [(size_t)B_ * SKV_ * DQ_];   // projected k  [B,SKV,H*DH]
__device__ float g_v  [(size_t)B_ * SKV_ * DQ_];   // projected v  [B,SKV,H*DH]
__device__ float g_att[(size_t)B_ * SQ_  * DQ_];   // attention out pre-Wo
__device__ int   g_mask_flag;                      // 0=u8, 1=i32, 2=f32

// ---------------------------------------------------------------------------
// Mask dtype probe: bool arrays can be shipped as u8, i32, or f32 depending on
// the harness's dtype mapping. Detect from the raw bytes (deterministic).
// ---------------------------------------------------------------------------
__global__ void probe_mask_kernel(const unsigned int* __restrict__ m)
{
    if (blockIdx.x != 0 || threadIdx.x != 0) return;
    int is_i32 = 1, is_f32 = 1;
    for (int i = 0; i < 4096; i++) {
        unsigned v = m[i];
        if (v > 1u) is_i32 = 0;
        if (v != 0u && v != 0x3F800000u) is_f32 = 0;
    }
    g_mask_flag = is_i32 ? 1 : (is_f32 ? 2 : 0);
}

__device__ __forceinline__ bool read_mask(const void* m, long i, int flag)
{
    if (flag == 1) return ((const int*)m)[i] != 0;
    if (flag == 2) return ((const float*)m)[i] != 0.0f;
    return ((const unsigned char*)m)[i] != 0;
}

// ---------------------------------------------------------------------------
// Generic tiled SGEMM:  C[M,N] = A[M,K] @ W[N,K]^T + bias[N]
// 128x128 block tile, BK=16, 256 threads, 8x8 per-thread micro-tile.
// Requires M%128==0, N%128==0, K%16==0 (all shapes here satisfy this).
// ---------------------------------------------------------------------------
__global__ __launch_bounds__(256)
void sgemm_bias_kernel(const float* __restrict__ A, const float* __restrict__ W,
                       const float* __restrict__ bias, float* __restrict__ C,
                       int M, int N, int K)
{
    __shared__ float As[16][128];
    __shared__ float Bs[16][128];

    const int tid = threadIdx.x;
    const int tn  = tid & 15;       // 16 thread cols
    const int tm  = tid >> 4;       // 16 thread rows
    const int m0  = blockIdx.y * 128;
    const int n0  = blockIdx.x * 128;

    float acc[8][8];
#pragma unroll
    for (int i = 0; i < 8; i++)
#pragma unroll
        for (int j = 0; j < 8; j++) acc[i][j] = 0.0f;

    for (int k0 = 0; k0 < K; k0 += 16) {
        // Cooperative loads: 128x16 tiles of A and W, transposed into smem.
#pragma unroll
        for (int t = 0; t < 2; t++) {
            int l = tid * 2 + t;           // 0..511
            int r = l >> 2;                // row within tile (0..127)
            int c = (l & 3) * 4;           // col group (0,4,8,12)
            float4 va = *(const float4*)(A + (long)(m0 + r) * K + k0 + c);
            As[c + 0][r] = va.x; As[c + 1][r] = va.y;
            As[c + 2][r] = va.z; As[c + 3][r] = va.w;
            float4 vb = *(const float4*)(W + (long)(n0 + r) * K + k0 + c);
            Bs[c + 0][r] = vb.x; Bs[c + 1][r] = vb.y;
            Bs[c + 2][r] = vb.z; Bs[c + 3][r] = vb.w;
        }
        __syncthreads();

#pragma unroll
        for (int k = 0; k < 16; k++) {
            float a[8], b[8];
#pragma unroll
            for (int i = 0; i < 8; i++) a[i] = As[k][tm * 8 + i];
#pragma unroll
            for (int j = 0; j < 8; j++) b[j] = Bs[k][tn * 8 + j];
#pragma unroll
            for (int i = 0; i < 8; i++)
#pragma unroll
                for (int j = 0; j < 8; j++)
                    acc[i][j] = fmaf(a[i], b[j], acc[i][j]);
        }
        __syncthreads();
    }

#pragma unroll
    for (int i = 0; i < 8; i++) {
        long row = (long)(m0 + tm * 8 + i);
#pragma unroll
        for (int j = 0; j < 8; j++) {
            int col = n0 + tn * 8 + j;
            C[row * N + col] = acc[i][j] + bias[col];
        }
    }
}

// ---------------------------------------------------------------------------
// Scores: S[b,h,q,kv] = (q_bh . k_bh) / 8, masked positions -> -1e9.
// Per (b,h): M=SQ(q) x N=SKV(kv), K=DH=64. Writes raw masked scores into the
// att_weights region of d_out (softmax kernel normalizes in-place after).
// ---------------------------------------------------------------------------
__global__ __launch_bounds__(256)
void attn_scores_kernel(const void* __restrict__ mask, float* __restrict__ Wt)
{
    __shared__ float As[16][128];
    __shared__ float Bs[16][128];

    const int bh = blockIdx.z;
    const int b  = bh >> 4;
    const int h  = bh & 15;
    const float* A  = g_q + (long)b * SQ_  * DQ_ + h * DH_;  // lda = DQ_
    const float* Bm = g_k + (long)b * SKV_ * DQ_ + h * DH_;  // ldb = DQ_

    const int tid = threadIdx.x;
    const int tn  = tid & 15;
    const int tm  = tid >> 4;
    const int m0  = blockIdx.y * 128;   // q tile
    const int n0  = blockIdx.x * 128;   // kv tile

    float acc[8][8];
#pragma unroll
    for (int i = 0; i < 8; i++)
#pragma unroll
        for (int j = 0; j < 8; j++) acc[i][j] = 0.0f;

    for (int k0 = 0; k0 < DH_; k0 += 16) {
#pragma unroll
        for (int t = 0; t < 2; t++) {
            int l = tid * 2 + t;
            int r = l >> 2;
            int c = (l & 3) * 4;
            float4 va = *(const float4*)(A + (long)(m0 + r) * DQ_ + k0 + c);
            As[c + 0][r] = va.x; As[c + 1][r] = va.y;
            As[c + 2][r] = va.z; As[c + 3][r] = va.w;
            float4 vb = *(const float4*)(Bm + (long)(n0 + r) * DQ_ + k0 + c);
            Bs[c + 0][r] = vb.x; Bs[c + 1][r] = vb.y;
            Bs[c + 2][r] = vb.z; Bs[c + 3][r] = vb.w;
        }
        __syncthreads();

#pragma unroll
        for (int k = 0; k < 16; k++) {
            float a[8], bb[8];
#pragma unroll
            for (int i = 0; i < 8; i++) a[i] = As[k][tm * 8 + i];
#pragma unroll
            for (int j = 0; j < 8; j++) bb[j] = Bs[k][tn * 8 + j];
#pragma unroll
            for (int i = 0; i < 8; i++)
#pragma unroll
                for (int j = 0; j < 8; j++)
                    acc[i][j] = fmaf(a[i], bb[j], acc[i][j]);
        }
        __syncthreads();
    }

    const int flag = g_mask_flag;
#pragma unroll
    for (int i = 0; i < 8; i++) {
        int m = m0 + tm * 8 + i;                       // q index
        long outb = ((long)bh * SQ_ + m) * SKV_;
#pragma unroll
        for (int j = 0; j < 8; j++) {
            int n = n0 + tn * 8 + j;                   // kv index
            float sv = acc[i][j] * 0.125f;             // 1/sqrt(DH=64)
            long mi = ((long)b * SKV_ + n) * SQ_ + m;  // att_mask[b, kv, q]
            if (read_mask(mask, mi, flag)) sv = -1.0e9f;
            Wt[outb + n] = sv;
        }
    }
}

// ---------------------------------------------------------------------------
// Row softmax over SKV=4096, in place, one block per row. Row kept in
// registers (16 elems/thread): 1 read + 1 write of the 1.07 GB buffer.
// ---------------------------------------------------------------------------
__global__ __launch_bounds__(256)
void softmax_kernel(float* __restrict__ Wt)
{
    __shared__ float shm[8];
    __shared__ float shs[8];
    __shared__ float bmx, bsum;

    const long row = blockIdx.x;          // B*H*SQ = 65536 rows
    float* p = Wt + row * SKV_;
    const int tid  = threadIdx.x;
    const int lane = tid & 31;
    const int wrp  = tid >> 5;

    float s[16];
    float mx = -3.4e38f;
#pragma unroll
    for (int i = 0; i < 16; i++) {
        s[i] = p[tid + (i << 8)];
        mx = fmaxf(mx, s[i]);
    }
#pragma unroll
    for (int o = 16; o; o >>= 1) mx = fmaxf(mx, __shfl_xor_sync(0xFFFFFFFFu, mx, o));
    if (lane == 0) shm[wrp] = mx;
    __syncthreads();
    if (tid == 0) {
        float v = shm[0];
#pragma unroll
        for (int i = 1; i < 8; i++) v = fmaxf(v, shm[i]);
        bmx = v;
    }
    __syncthreads();
    mx = bmx;

    float sum = 0.0f;
#pragma unroll
    for (int i = 0; i < 16; i++) {
        s[i] = __expf(s[i] - mx);
        sum += s[i];
    }
#pragma unroll
    for (int o = 16; o; o >>= 1) sum += __shfl_xor_sync(0xFFFFFFFFu, sum, o);
    if (lane == 0) shs[wrp] = sum;
    __syncthreads();
    if (tid == 0) {
        float v = shs[0];
#pragma unroll
        for (int i = 1; i < 8; i++) v += shs[i];
        bsum = v;
    }
    __syncthreads();
    const float inv = 1.0f / bsum;

#pragma unroll
    for (int i = 0; i < 16; i++) p[tid + (i << 8)] = s[i] * inv;
}

// ---------------------------------------------------------------------------
// PV: att[b,q,h*64+d] = sum_kv W[b,h,q,kv] * v[b,kv,h*64+d]
// Per (b,h): M=SQ x N=DH=64, K=SKV=4096. 128x64 block tile, 8x4 micro-tile.
// ---------------------------------------------------------------------------
__global__ __launch_bounds__(256)
void attn_pv_kernel(const float* __restrict__ Wt)
{
    __shared__ float Ws[16][128];
    __shared__ float Vs[16][64];

    const int bh = blockIdx.z;
    const int b  = bh >> 4;
    const int h  = bh & 15;
    const int m0 = blockIdx.y * 128;

    const float* Wrow = Wt  + (long)bh * SQ_ * SKV_;
    const float* V    = g_v + (long)b * SKV_ * DQ_ + h * DH_;

    const int tid = threadIdx.x;
    const int tn  = tid & 15;   // 16 * 4 = 64 cols
    const int tm  = tid >> 4;   // 16 * 8 = 128 rows

    float acc[8][4];
#pragma unroll
    for (int i = 0; i < 8; i++)
#pragma unroll
        for (int j = 0; j < 4; j++) acc[i][j] = 0.0f;

    for (int k0 = 0; k0 < SKV_; k0 += 16) {
        // W tile: 128 rows x 16 k
#pragma unroll
        for (int t = 0; t < 2; t++) {
            int l = tid * 2 + t;
            int r = l >> 2;
            int c = (l & 3) * 4;
            float4 va = *(const float4*)(Wrow + (long)(m0 + r) * SKV_ + k0 + c);
            Ws[c + 0][r] = va.x; Ws[c + 1][r] = va.y;
            Ws[c + 2][r] = va.z; Ws[c + 3][r] = va.w;
        }
        // V tile: 16 k x 64 d (one float4 per thread)
        {
            int r = tid >> 4;
            int c = (tid & 15) * 4;
            float4 vv = *(const float4*)(V + (long)(k0 + r) * DQ_ + c);
            *(float4*)&Vs[r][c] = vv;
        }
        __syncthreads();

#pragma unroll
        for (int k = 0; k < 16; k++) {
            float a[8];
#pragma unroll
            for (int i = 0; i < 8; i++) a[i] = Ws[k][tm * 8 + i];
            float4 bv = *(const float4*)&Vs[k][tn * 4];
            float bb[4] = {bv.x, bv.y, bv.z, bv.w};
#pragma unroll
            for (int i = 0; i < 8; i++)
#pragma unroll
                for (int j = 0; j < 4; j++)
                    acc[i][j] = fmaf(a[i], bb[j], acc[i][j]);
        }
        __syncthreads();
    }

#pragma unroll
    for (int i = 0; i < 8; i++) {
        long row = (long)b * SQ_ + m0 + tm * 8 + i;
#pragma unroll
        for (int j = 0; j < 4; j++)
            g_att[row * DQ_ + h * DH_ + tn * 4 + j] = acc[i][j];
    }
}

// ---------------------------------------------------------------------------
// Launch
// ---------------------------------------------------------------------------
extern "C" void kernel_launch(void* const* d_in, const int* in_sizes, int n_in,
                              void* d_out, int out_size)
{
    (void)in_sizes; (void)n_in; (void)out_size;

    const float* Q   = (const float*)d_in[0];
    const float* K   = (const float*)d_in[1];
    const float* V   = (const float*)d_in[2];
    const void*  Msk = d_in[3];
    const float* Wq  = (const float*)d_in[4];
    const float* bq  = (const float*)d_in[5];
    const float* Wk  = (const float*)d_in[6];
    const float* bk  = (const float*)d_in[7];
    const float* Wv  = (const float*)d_in[8];
    const float* bv  = (const float*)d_in[9];
    const float* Wo  = (const float*)d_in[10];
    const float* bo  = (const float*)d_in[11];

    float* out = (float*)d_out;                          // [B,SQ,DOUT]
    float* Wt  = out + (size_t)B_ * SQ_ * DOUT_;         // [B,H,SQ,SKV]

    float *pq, *pk, *pv, *pa;
    cudaGetSymbolAddress((void**)&pq, g_q);
    cudaGetSymbolAddress((void**)&pk, g_k);
    cudaGetSymbolAddress((void**)&pv, g_v);
    cudaGetSymbolAddress((void**)&pa, g_att);

    // 0) mask dtype probe
    probe_mask_kernel<<<1, 1>>>((const unsigned int*)Msk);

    // 1) projections
    sgemm_bias_kernel<<<dim3(DQ_ / 128, (B_ * SQ_) / 128), 256>>>(
        Q, Wq, bq, pq, B_ * SQ_, DQ_, DQ_);
    sgemm_bias_kernel<<<dim3(DQ_ / 128, (B_ * SKV_) / 128), 256>>>(
        K, Wk, bk, pk, B_ * SKV_, DQ_, DKV_);
    sgemm_bias_kernel<<<dim3(DQ_ / 128, (B_ * SKV_) / 128), 256>>>(
        V, Wv, bv, pv, B_ * SKV_, DQ_, DKV_);

    // 2) scores (masked, pre-softmax) -> weights region of d_out
    attn_scores_kernel<<<dim3(SKV_ / 128, SQ_ / 128, B_ * H_), 256>>>(Msk, Wt);

    // 3) row softmax in place
    softmax_kernel<<<B_ * H_ * SQ_, 256>>>(Wt);

    // 4) PV
    attn_pv_kernel<<<dim3(1, SQ_ / 128, B_ * H_), 256>>>(Wt);

    // 5) output projection -> front of d_out
    sgemm_bias_kernel<<<dim3(DOUT_ / 128, (B_ * SQ_) / 128), 256>>>(
        pa, Wo, bo, out, B_ * SQ_, DOUT_, DQ_);
}

// round 5
// speedup vs baseline: 1.5827x; 1.5827x over previous
#include <cuda_runtime.h>
#include <cuda_bf16.h>
#include <cstdint>
#include <math.h>

// Problem constants
#define B_    4
#define SQ_   1024
#define SKV_  4096
#define DQ_   1024
#define DKV_  768
#define H_    16
#define DH_   64
#define DOUT_ 256

// ---------------------------------------------------------------------------
// Scratch (static device globals)
// ---------------------------------------------------------------------------
__device__ float g_q  [(size_t)B_ * SQ_  * DQ_];
__device__ float g_k  [(size_t)B_ * SKV_ * DQ_];
__device__ float g_v  [(size_t)B_ * SKV_ * DQ_];
__device__ float g_vt [(size_t)B_ * DQ_  * SKV_];   // V transposed: [b][ch][skv]
__device__ float g_att[(size_t)B_ * SQ_  * DQ_];
__device__ int   g_mask_flag;                       // 0=u8, 1=i32, 2=f32

#define SWZ(o) ((o) ^ (((o) >> 3) & 0x70))

// ---------------------------------------------------------------------------
// Mask dtype probe
// ---------------------------------------------------------------------------
__global__ void probe_mask_kernel(const unsigned int* __restrict__ m)
{
    if (blockIdx.x != 0 || threadIdx.x != 0) return;
    int is_i32 = 1, is_f32 = 1;
    for (int i = 0; i < 4096; i++) {
        unsigned v = m[i];
        if (v > 1u) is_i32 = 0;
        if (v != 0u && v != 0x3F800000u) is_f32 = 0;
    }
    g_mask_flag = is_i32 ? 1 : (is_f32 ? 2 : 0);
}

__device__ __forceinline__ bool read_mask(const void* m, long i, int flag)
{
    if (flag == 1) return ((const int*)m)[i] != 0;
    if (flag == 2) return ((const float*)m)[i] != 0.0f;
    return ((const unsigned char*)m)[i] != 0;
}

// ---------------------------------------------------------------------------
// MMA / ldmatrix primitives (baseline PTX, no sm_103a features)
// ---------------------------------------------------------------------------
__device__ __forceinline__ uint32_t smem_to_u32(const void* p) {
    uint32_t a;
    asm("{ .reg .u64 t; cvta.to.shared.u64 t, %1; cvt.u32.u64 %0, t; }"
        : "=r"(a) : "l"(p));
    return a;
}

__device__ __forceinline__ void ldm_x4(uint32_t addr, uint32_t* r) {
    asm volatile("ldmatrix.sync.aligned.m8n8.x4.shared.b16 {%0,%1,%2,%3}, [%4];"
                 : "=r"(r[0]), "=r"(r[1]), "=r"(r[2]), "=r"(r[3]) : "r"(addr));
}

__device__ __forceinline__ void mma_bf16(float* d, const uint32_t* a,
                                         uint32_t b0, uint32_t b1) {
    asm volatile(
        "mma.sync.aligned.m16n8k16.row.col.f32.bf16.bf16.f32 "
        "{%0,%1,%2,%3}, {%4,%5,%6,%7}, {%8,%9}, {%0,%1,%2,%3};"
        : "+f"(d[0]), "+f"(d[1]), "+f"(d[2]), "+f"(d[3])
        : "r"(a[0]), "r"(a[1]), "r"(a[2]), "r"(a[3]), "r"(b0), "r"(b1));
}

// ---------------------------------------------------------------------------
// fp32 -> bf16 hi/lo split conversion + swizzled STS
// ---------------------------------------------------------------------------
__device__ __forceinline__ uint32_t pk2(__nv_bfloat16 a, __nv_bfloat16 b)
{
    return (uint32_t)__bfloat16_as_ushort(a) | ((uint32_t)__bfloat16_as_ushort(b) << 16);
}

__device__ __forceinline__ void cvt1(float4 v, char* hb, char* lb, int r, int cg)
{
    __nv_bfloat16 h0 = __float2bfloat16(v.x);
    __nv_bfloat16 h1 = __float2bfloat16(v.y);
    __nv_bfloat16 h2 = __float2bfloat16(v.z);
    __nv_bfloat16 h3 = __float2bfloat16(v.w);
    __nv_bfloat16 l0 = __float2bfloat16(v.x - __bfloat162float(h0));
    __nv_bfloat16 l1 = __float2bfloat16(v.y - __bfloat162float(h1));
    __nv_bfloat16 l2 = __float2bfloat16(v.z - __bfloat162float(h2));
    __nv_bfloat16 l3 = __float2bfloat16(v.w - __bfloat162float(h3));
    unsigned off = SWZ((unsigned)(r * 128 + (cg << 1)));
    *(uint2*)(hb + off) = make_uint2(pk2(h0, h1), pk2(h2, h3));
    *(uint2*)(lb + off) = make_uint2(pk2(l0, l1), pk2(l2, l3));
}

// ---------------------------------------------------------------------------
// HMMA split-bf16 GEMM.  D[128, NT] per CTA = A[128,K] @ B[NT,K]^T (+epilogue)
// MODE 0: C = A@B^T + bias  (projections / Wo)
// MODE 1: scores per z=(b,h): C = mask ? -1e9 : A@B^T * 0.125
// MODE 2: PV per z=(b,h): A=Wt rows, B=g_vt rows (both K-contiguous)
// ---------------------------------------------------------------------------
template<int NT, int MODE>
__global__ void __launch_bounds__(256, 1)
hgemm_kernel(const float* __restrict__ A0, int lda,
             const float* __restrict__ B0, int ldb,
             const float* __restrict__ bias,
             float* __restrict__ C0, int ldc,
             int Kdim, const void* __restrict__ mask)
{
    extern __shared__ char smem[];
    constexpr int NF     = NT / 16;              // n-frags (n8 pairs) per warp
    constexpr int NBF4   = NT / 16;              // B staging float4 per thread
    constexpr unsigned MASKSZ = (MODE == 1) ? 16384u : 0u;
    constexpr unsigned ABYTES = 128 * 128;       // bf16 tile 128 rows x 128B
    constexpr unsigned BBYTES = NT * 128;
    constexpr unsigned BUFSZ  = 2 * ABYTES + 2 * BBYTES;

    const uint32_t sbase = smem_to_u32(smem);
    const int tid = threadIdx.x;
    const int wid = tid >> 5, lid = tid & 31;
    const int wm = wid & 3, wn = wid >> 2;       // 4(m) x 2(n) warp grid
    const int m0 = blockIdx.y * 128, n0 = blockIdx.x * NT, z = blockIdx.z;

    // mode-specific base pointers
    const float* Ap; const float* Bp; float* Cp;
    int LDA, LDB, LDC;
    if (MODE == 0) {
        Ap = A0 + (long)m0 * lda;                         LDA = lda;
        Bp = B0 + (long)n0 * ldb;                         LDB = ldb;
        Cp = C0 + (long)m0 * ldc + n0;                    LDC = ldc;
    } else if (MODE == 1) {
        int b = z >> 4, h = z & 15;
        Ap = A0 + ((long)b * SQ_  + m0) * DQ_ + h * DH_;  LDA = DQ_;
        Bp = B0 + ((long)b * SKV_ + n0) * DQ_ + h * DH_;  LDB = DQ_;
        Cp = C0 + ((long)z * SQ_  + m0) * SKV_ + n0;      LDC = SKV_;
    } else {
        int b = z >> 4, h = z & 15;
        Ap = A0 + ((long)z * SQ_ + m0) * SKV_;            LDA = SKV_;
        Bp = B0 + ((long)(b * DQ_ + h * DH_)) * SKV_;     LDB = SKV_;
        Cp = C0 + ((long)b * SQ_ + m0) * DQ_ + h * DH_;   LDC = DQ_;
    }

    // mask tile -> smem u8 [kv 128][q 128] (scores only)
    if (MODE == 1) {
        const int flag = g_mask_flag;
        const int b = z >> 4;
        for (int i = tid; i < 128 * 128; i += 256) {
            int kv = i >> 7, q = i & 127;
            bool mm = read_mask(mask, ((long)b * SKV_ + n0 + kv) * SQ_ + m0 + q, flag);
            smem[i] = mm ? 1 : 0;
        }
    }

    // accumulators
    float dc[2 * NF][4];
#pragma unroll
    for (int i = 0; i < 2 * NF; i++)
#pragma unroll
        for (int j = 0; j < 4; j++) dc[i][j] = 0.0f;

    float4 stg[8 + NBF4];

    const int ns = Kdim >> 6;

    // ---- pipeline helpers ----
    auto ldg_slab = [&](int s) {
        const float* As = Ap + s * 64;
        const float* Bs = Bp + s * 64;
#pragma unroll
        for (int i = 0; i < 8; i++) {
            int f = tid + i * 256, r = f >> 4, cg = (f & 15) << 2;
            stg[i] = *(const float4*)(As + (long)r * LDA + cg);
        }
#pragma unroll
        for (int i = 0; i < NBF4; i++) {
            int f = tid + i * 256, r = f >> 4, cg = (f & 15) << 2;
            stg[8 + i] = *(const float4*)(Bs + (long)r * LDB + cg);
        }
    };
    auto cvt_sts = [&](int buf) {
        char* base = smem + MASKSZ + buf * BUFSZ;
        char* ah = base;
        char* al = base + ABYTES;
        char* bh = base + 2 * ABYTES;
        char* bl = bh + BBYTES;
#pragma unroll
        for (int i = 0; i < 8; i++) {
            int f = tid + i * 256;
            cvt1(stg[i], ah, al, f >> 4, (f & 15) << 2);
        }
#pragma unroll
        for (int i = 0; i < NBF4; i++) {
            int f = tid + i * 256;
            cvt1(stg[8 + i], bh, bl, f >> 4, (f & 15) << 2);
        }
    };
    auto compute = [&](int buf) {
        const uint32_t sA  = sbase + MASKSZ + buf * BUFSZ;
        const uint32_t sAl = sA + ABYTES;
        const uint32_t sB  = sA + 2 * ABYTES;
        const uint32_t sBl = sB + BBYTES;
        const int lr = lid & 15, hsel = (lid >> 4) << 4;   // 0 or 16 bytes (k+8)
#pragma unroll
        for (int ks = 0; ks < 4; ks++) {
            const int kb = ks * 32 + hsel;
            uint32_t aH[2][4], aL[2][4];
#pragma unroll
            for (int i = 0; i < 2; i++) {
                unsigned off = SWZ((unsigned)((wm * 32 + i * 16 + lr) * 128 + kb));
                ldm_x4(sA + off, aH[i]);
                ldm_x4(sAl + off, aL[i]);
            }
#pragma unroll
            for (int jj = 0; jj < NF / 2; jj++) {
                unsigned off = SWZ((unsigned)((wn * (NT / 2) + jj * 16 + lr) * 128 + kb));
                uint32_t bH[4], bL[4];
                ldm_x4(sB + off, bH);
                ldm_x4(sBl + off, bL);
#pragma unroll
                for (int i = 0; i < 2; i++) {
#pragma unroll
                    for (int t = 0; t < 2; t++) {
                        float* d = dc[i * NF + jj * 2 + t];
                        mma_bf16(d, aH[i], bH[t], bH[t + 2]);
                        mma_bf16(d, aH[i], bL[t], bL[t + 2]);
                        mma_bf16(d, aL[i], bH[t], bH[t + 2]);
                    }
                }
            }
        }
    };

    // ---- software pipeline ----
    ldg_slab(0);
    cvt_sts(0);
    __syncthreads();
    for (int s = 0; s < ns; s++) {
        if (s + 1 < ns) ldg_slab(s + 1);
        compute(s & 1);
        if (s + 1 < ns) cvt_sts((s + 1) & 1);
        __syncthreads();
    }

    // ---- epilogue ----
#pragma unroll
    for (int i = 0; i < 2; i++) {
#pragma unroll
        for (int f = 0; f < NF; f++) {
            const float* d = dc[i * NF + f];
            int rl = wm * 32 + i * 16 + (lid >> 2);
            int cl = wn * (NT / 2) + f * 8 + ((lid & 3) << 1);
            if (MODE == 0) {
                float2 bb = *(const float2*)(bias + n0 + cl);
                *(float2*)(Cp + (long)rl * LDC + cl) =
                    make_float2(d[0] + bb.x, d[1] + bb.y);
                *(float2*)(Cp + (long)(rl + 8) * LDC + cl) =
                    make_float2(d[2] + bb.x, d[3] + bb.y);
            } else if (MODE == 1) {
                const unsigned char* mk = (const unsigned char*)smem;
                float2 o0, o1;
                o0.x = mk[(cl + 0) * 128 + rl]     ? -1.0e9f : d[0] * 0.125f;
                o0.y = mk[(cl + 1) * 128 + rl]     ? -1.0e9f : d[1] * 0.125f;
                o1.x = mk[(cl + 0) * 128 + rl + 8] ? -1.0e9f : d[2] * 0.125f;
                o1.y = mk[(cl + 1) * 128 + rl + 8] ? -1.0e9f : d[3] * 0.125f;
                *(float2*)(Cp + (long)rl * LDC + cl) = o0;
                *(float2*)(Cp + (long)(rl + 8) * LDC + cl) = o1;
            } else {
                *(float2*)(Cp + (long)rl * LDC + cl) = make_float2(d[0], d[1]);
                *(float2*)(Cp + (long)(rl + 8) * LDC + cl) = make_float2(d[2], d[3]);
            }
        }
    }
}

// ---------------------------------------------------------------------------
// V transpose: g_v [b][kv][ch] -> g_vt [b][ch][skv]
// ---------------------------------------------------------------------------
__global__ __launch_bounds__(256)
void transpose_v_kernel(const float* __restrict__ v, float* __restrict__ vt)
{
    __shared__ float t[32][33];
    const int b   = blockIdx.z;
    const int kv0 = blockIdx.x * 32, ch0 = blockIdx.y * 32;
    const int x = threadIdx.x, y = threadIdx.y;      // 32 x 8
#pragma unroll
    for (int i = y; i < 32; i += 8)
        t[i][x] = v[((long)b * SKV_ + kv0 + i) * DQ_ + ch0 + x];
    __syncthreads();
#pragma unroll
    for (int i = y; i < 32; i += 8)
        vt[((long)b * DQ_ + ch0 + i) * SKV_ + kv0 + x] = t[x][i];
}

// ---------------------------------------------------------------------------
// Row softmax over SKV=4096, in place
// ---------------------------------------------------------------------------
__global__ __launch_bounds__(256)
void softmax_kernel(float* __restrict__ Wt)
{
    __shared__ float shm[8];
    __shared__ float shs[8];
    __shared__ float bmx, bsum;

    const long row = blockIdx.x;
    float* p = Wt + row * SKV_;
    const int tid  = threadIdx.x;
    const int lane = tid & 31;
    const int wrp  = tid >> 5;

    float s[16];
    float mx = -3.4e38f;
#pragma unroll
    for (int i = 0; i < 16; i++) {
        s[i] = p[tid + (i << 8)];
        mx = fmaxf(mx, s[i]);
    }
#pragma unroll
    for (int o = 16; o; o >>= 1) mx = fmaxf(mx, __shfl_xor_sync(0xFFFFFFFFu, mx, o));
    if (lane == 0) shm[wrp] = mx;
    __syncthreads();
    if (tid == 0) {
        float v = shm[0];
#pragma unroll
        for (int i = 1; i < 8; i++) v = fmaxf(v, shm[i]);
        bmx = v;
    }
    __syncthreads();
    mx = bmx;

    float sum = 0.0f;
#pragma unroll
    for (int i = 0; i < 16; i++) {
        s[i] = __expf(s[i] - mx);
        sum += s[i];
    }
#pragma unroll
    for (int o = 16; o; o >>= 1) sum += __shfl_xor_sync(0xFFFFFFFFu, sum, o);
    if (lane == 0) shs[wrp] = sum;
    __syncthreads();
    if (tid == 0) {
        float v = shs[0];
#pragma unroll
        for (int i = 1; i < 8; i++) v += shs[i];
        bsum = v;
    }
    __syncthreads();
    const float inv = 1.0f / bsum;

#pragma unroll
    for (int i = 0; i < 16; i++) p[tid + (i << 8)] = s[i] * inv;
}

// ---------------------------------------------------------------------------
// Launch
// ---------------------------------------------------------------------------
extern "C" void kernel_launch(void* const* d_in, const int* in_sizes, int n_in,
                              void* d_out, int out_size)
{
    (void)in_sizes; (void)n_in; (void)out_size;

    const float* Q   = (const float*)d_in[0];
    const float* K   = (const float*)d_in[1];
    const float* V   = (const float*)d_in[2];
    const void*  Msk = d_in[3];
    const float* Wq  = (const float*)d_in[4];
    const float* bq  = (const float*)d_in[5];
    const float* Wk  = (const float*)d_in[6];
    const float* bk  = (const float*)d_in[7];
    const float* Wv  = (const float*)d_in[8];
    const float* bv  = (const float*)d_in[9];
    const float* Wo  = (const float*)d_in[10];
    const float* bo  = (const float*)d_in[11];

    float* out = (float*)d_out;                       // [B,SQ,DOUT]
    float* Wt  = out + (size_t)B_ * SQ_ * DOUT_;      // [B,H,SQ,SKV]

    float *pq, *pk, *pv, *pvt, *pa;
    cudaGetSymbolAddress((void**)&pq,  g_q);
    cudaGetSymbolAddress((void**)&pk,  g_k);
    cudaGetSymbolAddress((void**)&pv,  g_v);
    cudaGetSymbolAddress((void**)&pvt, g_vt);
    cudaGetSymbolAddress((void**)&pa,  g_att);

    const int SM0 = 2 * (2 * 16384 + 2 * 16384);           // 131072 (MODE0 NT128)
    const int SM1 = 16384 + SM0;                           // 147456 (MODE1)
    const int SM2 = 2 * (2 * 16384 + 2 * 8192);            //  98304 (MODE2 NT64)
    cudaFuncSetAttribute(hgemm_kernel<128, 0>, cudaFuncAttributeMaxDynamicSharedMemorySize, SM0);
    cudaFuncSetAttribute(hgemm_kernel<128, 1>, cudaFuncAttributeMaxDynamicSharedMemorySize, SM1);
    cudaFuncSetAttribute(hgemm_kernel<64, 2>,  cudaFuncAttributeMaxDynamicSharedMemorySize, SM2);

    // 0) mask dtype probe
    probe_mask_kernel<<<1, 1>>>((const unsigned int*)Msk);

    // 1) projections (split-bf16 HMMA)
    hgemm_kernel<128, 0><<<dim3(DQ_ / 128, (B_ * SQ_) / 128, 1), 256, SM0>>>(
        Q, DQ_, Wq, DQ_, bq, pq, DQ_, DQ_, nullptr);
    hgemm_kernel<128, 0><<<dim3(DQ_ / 128, (B_ * SKV_) / 128, 1), 256, SM0>>>(
        K, DKV_, Wk, DKV_, bk, pk, DQ_, DKV_, nullptr);
    hgemm_kernel<128, 0><<<dim3(DQ_ / 128, (B_ * SKV_) / 128, 1), 256, SM0>>>(
        V, DKV_, Wv, DKV_, bv, pv, DQ_, DKV_, nullptr);

    // 1b) transpose projected V for K-contiguous PV operand
    transpose_v_kernel<<<dim3(SKV_ / 32, DQ_ / 32, B_), dim3(32, 8)>>>(pv, pvt);

    // 2) masked scores -> weights region of d_out
    hgemm_kernel<128, 1><<<dim3(SKV_ / 128, SQ_ / 128, B_ * H_), 256, SM1>>>(
        pq, 0, pk, 0, nullptr, Wt, 0, DH_, Msk);

    // 3) row softmax in place
    softmax_kernel<<<B_ * H_ * SQ_, 256>>>(Wt);

    // 4) PV
    hgemm_kernel<64, 2><<<dim3(1, SQ_ / 128, B_ * H_), 256, SM2>>>(
        Wt, 0, pvt, 0, nullptr, pa, 0, SKV_, nullptr);

    // 5) output projection
    hgemm_kernel<128, 0><<<dim3(DOUT_ / 128, (B_ * SQ_) / 128, 1), 256, SM0>>>(
        pa, DQ_, Wo, DQ_, bo, out, DOUT_, DQ_, nullptr);
}